// round 1
// baseline (speedup 1.0000x reference)
#include <cuda_runtime.h>
#include <cstdint>

#define N_TOK 4096
#define D_IN  1024
#define D_HID 4096
#define D_OUT 1024
#define N_EXP 8

// ---------------- scratch (device globals; no runtime allocation) ----------------
__device__ float g_H[(size_t)N_TOK * 2 * D_HID];   // hidden acts per (token,k) slot
__device__ float g_Y[(size_t)N_TOK * 2 * D_OUT];   // expert outputs per slot
__device__ float g_topk_w[N_TOK * 2];
__device__ int   g_count[N_EXP];
__device__ int   g_slots[N_EXP * N_TOK];           // slot = 2*token + k

// ---------------- helpers ----------------
__device__ __forceinline__ uint32_t f2tf32(float f) {
    uint32_t u;
    asm("cvt.rna.tf32.f32 %0, %1;" : "=r"(u) : "f"(f));
    return u;
}

__device__ __forceinline__ uint32_t sptr(const void* p) {
    return (uint32_t)__cvta_generic_to_shared(p);
}

__device__ __forceinline__ void cpa16(uint32_t s, const void* g) {
    asm volatile("cp.async.cg.shared.global [%0], [%1], 16;\n" :: "r"(s), "l"(g));
}

__device__ __forceinline__ void mma_tf32(float* d, const uint32_t* a, const uint32_t* b) {
    asm volatile(
        "mma.sync.aligned.m16n8k8.row.col.f32.tf32.tf32.f32 "
        "{%0,%1,%2,%3}, {%4,%5,%6,%7}, {%8,%9}, {%0,%1,%2,%3};"
        : "+f"(d[0]), "+f"(d[1]), "+f"(d[2]), "+f"(d[3])
        : "r"(a[0]), "r"(a[1]), "r"(a[2]), "r"(a[3]),
          "r"(b[0]), "r"(b[1]));
}

// ---------------- init: zero expert counters ----------------
__global__ void init_kernel() {
    if (threadIdx.x < N_EXP) g_count[threadIdx.x] = 0;
}

// ---------------- gating: softmax -> top2 -> renorm softmax -> scatter ----------------
__global__ void gating_kernel(const float* __restrict__ x,
                              const float* __restrict__ Wg,
                              const float* __restrict__ bg) {
    const int t    = blockIdx.x * 8 + (threadIdx.x >> 5);
    const int lane = threadIdx.x & 31;

    float acc[8];
#pragma unroll
    for (int e = 0; e < 8; e++) acc[e] = 0.f;

    const float* xr = x + (size_t)t * D_IN;
    for (int d = lane; d < D_IN; d += 32) {
        float xv = xr[d];
        float4 w0 = *(const float4*)(Wg + d * 8);
        float4 w1 = *(const float4*)(Wg + d * 8 + 4);
        acc[0] += xv * w0.x; acc[1] += xv * w0.y;
        acc[2] += xv * w0.z; acc[3] += xv * w0.w;
        acc[4] += xv * w1.x; acc[5] += xv * w1.y;
        acc[6] += xv * w1.z; acc[7] += xv * w1.w;
    }
#pragma unroll
    for (int off = 16; off > 0; off >>= 1)
#pragma unroll
        for (int e = 0; e < 8; e++)
            acc[e] += __shfl_xor_sync(0xFFFFFFFFu, acc[e], off);

    if (lane == 0) {
        float l[8];
#pragma unroll
        for (int e = 0; e < 8; e++) l[e] = acc[e] + bg[e];
        float mx = l[0];
#pragma unroll
        for (int e = 1; e < 8; e++) mx = fmaxf(mx, l[e]);
        float p[8], s = 0.f;
#pragma unroll
        for (int e = 0; e < 8; e++) { p[e] = expf(l[e] - mx); s += p[e]; }
        float inv = 1.f / s;
#pragma unroll
        for (int e = 0; e < 8; e++) p[e] *= inv;

        // top-2 (strict > keeps lowest index on ties, matching jax.lax.top_k)
        int i0 = 0; float v0 = p[0];
#pragma unroll
        for (int e = 1; e < 8; e++) if (p[e] > v0) { v0 = p[e]; i0 = e; }
        int i1 = -1; float v1 = -1.f;
#pragma unroll
        for (int e = 0; e < 8; e++) if (e != i0 && p[e] > v1) { v1 = p[e]; i1 = e; }

        // softmax over the two selected gate probabilities
        float e1 = expf(v1 - v0);
        float den = 1.f / (1.f + e1);
        float w0 = den;
        float w1 = e1 * den;

        int p0 = atomicAdd(&g_count[i0], 1);
        g_slots[i0 * N_TOK + p0] = 2 * t;
        int p1 = atomicAdd(&g_count[i1], 1);
        g_slots[i1 * N_TOK + p1] = 2 * t + 1;
        g_topk_w[2 * t]     = w0;
        g_topk_w[2 * t + 1] = w1;
    }
}

// ---------------- grouped GEMM (tf32 mma.sync), 128x128x16 tiles ----------------
// FIRST=true : A = gathered x rows [cnt, 1024],  B = W1[e] [1024,4096], out = relu(.+b1) -> g_H[slot]
// FIRST=false: A = gathered g_H rows [cnt,4096], B = W2[e] [4096,1024], out = .+b2      -> g_Y[slot]
template <bool FIRST>
__global__ void __launch_bounds__(128, 2)
ffn_kernel(const float* __restrict__ X,
           const float* __restrict__ W,
           const float* __restrict__ Bias) {
    constexpr int K  = FIRST ? D_IN : D_HID;
    constexpr int N  = FIRST ? D_HID : D_OUT;
    constexpr int BM = 128, BN = 128, BK = 16;
    constexpr int ASTR = BK + 4;   // 20: frag bank = (4*row + col) mod 32 -> conflict-free
    constexpr int BSTR = BN + 8;   // 136: frag bank = (8*k + n) mod 32   -> conflict-free
    constexpr int NS = K / BK;

    const int e   = blockIdx.z;
    const int cnt = g_count[e];
    const int m0  = blockIdx.y * BM;
    if (m0 >= cnt) return;
    const int rows = min(BM, cnt - m0);
    const int n0   = blockIdx.x * BN;

    const int tid  = threadIdx.x;
    const int lane = tid & 31;
    const int warp = tid >> 5;
    const int wm = warp >> 1;   // 0..1 over M
    const int wn = warp & 1;    // 0..1 over N

    __shared__ float sA[2][BM * ASTR];
    __shared__ float sB[2][BK * BSTR];
    __shared__ int   sSlot[BM];

    sSlot[tid] = g_slots[e * N_TOK + m0 + ((tid < rows) ? tid : 0)];
    __syncthreads();

    const float* Wb = W + (size_t)e * K * N + n0;

    auto stage = [&](int s, int b) {
        const int k0 = s * BK;
#pragma unroll
        for (int i = 0; i < 4; i++) {          // A: 128 rows x 16 cols
            int idx = i * 128 + tid;
            int row = idx >> 2;
            int c4  = (idx & 3) * 4;
            int slot = sSlot[row];
            const float* g = FIRST
                ? (X   + (size_t)(slot >> 1) * D_IN  + k0 + c4)
                : (g_H + (size_t)slot        * D_HID + k0 + c4);
            cpa16(sptr(&sA[b][row * ASTR + c4]), g);
        }
#pragma unroll
        for (int i = 0; i < 4; i++) {          // B: 16 rows x 128 cols
            int idx = i * 128 + tid;
            int kr  = idx >> 5;
            int c4  = (idx & 31) * 4;
            cpa16(sptr(&sB[b][kr * BSTR + c4]), Wb + (size_t)(k0 + kr) * N + c4);
        }
    };

    float acc[4][8][4];
#pragma unroll
    for (int a = 0; a < 4; a++)
#pragma unroll
        for (int b = 0; b < 8; b++)
#pragma unroll
            for (int c = 0; c < 4; c++) acc[a][b][c] = 0.f;

    stage(0, 0);
    asm volatile("cp.async.commit_group;\n");

    for (int s = 0; s < NS; ++s) {
        if (s + 1 < NS) {
            stage(s + 1, (s + 1) & 1);
            asm volatile("cp.async.commit_group;\n");
            asm volatile("cp.async.wait_group 1;\n");
        } else {
            asm volatile("cp.async.wait_group 0;\n");
        }
        __syncthreads();

        const float* A = sA[s & 1];
        const float* B = sB[s & 1];
#pragma unroll
        for (int ks = 0; ks < BK / 8; ++ks) {
            uint32_t af[4][4];
#pragma unroll
            for (int mf = 0; mf < 4; ++mf) {
                int r = wm * 64 + mf * 16 + (lane >> 2);
                int c = ks * 8 + (lane & 3);
                af[mf][0] = f2tf32(A[r       * ASTR + c]);
                af[mf][1] = f2tf32(A[(r + 8) * ASTR + c]);
                af[mf][2] = f2tf32(A[r       * ASTR + c + 4]);
                af[mf][3] = f2tf32(A[(r + 8) * ASTR + c + 4]);
            }
            uint32_t bf[8][2];
#pragma unroll
            for (int nf = 0; nf < 8; ++nf) {
                int col = wn * 64 + nf * 8 + (lane >> 2);
                int kr  = ks * 8 + (lane & 3);
                bf[nf][0] = f2tf32(B[kr       * BSTR + col]);
                bf[nf][1] = f2tf32(B[(kr + 4) * BSTR + col]);
            }
#pragma unroll
            for (int mf = 0; mf < 4; ++mf)
#pragma unroll
                for (int nf = 0; nf < 8; ++nf)
                    mma_tf32(acc[mf][nf], af[mf], bf[nf]);
        }
        __syncthreads();
    }

    // epilogue: bias (+relu for layer 1), scatter to slot rows
#pragma unroll
    for (int mf = 0; mf < 4; ++mf) {
        int rl = wm * 64 + mf * 16 + (lane >> 2);
#pragma unroll
        for (int nf = 0; nf < 8; ++nf) {
            int n = n0 + wn * 64 + nf * 8 + 2 * (lane & 3);
            float2 bv = *(const float2*)(Bias + (size_t)e * N + n);
            float v00 = acc[mf][nf][0] + bv.x;
            float v01 = acc[mf][nf][1] + bv.y;
            float v10 = acc[mf][nf][2] + bv.x;
            float v11 = acc[mf][nf][3] + bv.y;
            if (FIRST) {
                v00 = fmaxf(v00, 0.f); v01 = fmaxf(v01, 0.f);
                v10 = fmaxf(v10, 0.f); v11 = fmaxf(v11, 0.f);
                if (rl < rows) {
                    int slot = sSlot[rl];
                    *(float2*)(g_H + (size_t)slot * D_HID + n) = make_float2(v00, v01);
                }
                if (rl + 8 < rows) {
                    int slot = sSlot[rl + 8];
                    *(float2*)(g_H + (size_t)slot * D_HID + n) = make_float2(v10, v11);
                }
            } else {
                if (rl < rows) {
                    int slot = sSlot[rl];
                    *(float2*)(g_Y + (size_t)slot * D_OUT + n) = make_float2(v00, v01);
                }
                if (rl + 8 < rows) {
                    int slot = sSlot[rl + 8];
                    *(float2*)(g_Y + (size_t)slot * D_OUT + n) = make_float2(v10, v11);
                }
            }
        }
    }
}

// ---------------- combine: out[t] = w0*Y[2t] + w1*Y[2t+1] ----------------
__global__ void combine_kernel(float* __restrict__ out) {
    const int t = blockIdx.x;
    const float w0 = g_topk_w[2 * t];
    const float w1 = g_topk_w[2 * t + 1];
    const float4* y0 = (const float4*)(g_Y + (size_t)(2 * t)     * D_OUT);
    const float4* y1 = (const float4*)(g_Y + (size_t)(2 * t + 1) * D_OUT);
    float4* o = (float4*)(out + (size_t)t * D_OUT);
    for (int i = threadIdx.x; i < D_OUT / 4; i += blockDim.x) {
        float4 a = y0[i], b = y1[i];
        float4 r;
        r.x = w0 * a.x + w1 * b.x;
        r.y = w0 * a.y + w1 * b.y;
        r.z = w0 * a.z + w1 * b.z;
        r.w = w0 * a.w + w1 * b.w;
        o[i] = r;
    }
}

// ---------------- launch ----------------
extern "C" void kernel_launch(void* const* d_in, const int* in_sizes, int n_in,
                              void* d_out, int out_size) {
    const float* x  = (const float*)d_in[0];
    const float* W1 = (const float*)d_in[1];
    const float* b1 = (const float*)d_in[2];
    const float* W2 = (const float*)d_in[3];
    const float* b2 = (const float*)d_in[4];
    const float* Wg = (const float*)d_in[5];
    const float* bg = (const float*)d_in[6];
    float* out = (float*)d_out;

    init_kernel<<<1, 32>>>();
    gating_kernel<<<N_TOK / 8, 256>>>(x, Wg, bg);
    // worst-case M tiles per expert = N_TOK/128 = 32; inactive CTAs exit early
    ffn_kernel<true ><<<dim3(D_HID / 128, N_TOK / 128, N_EXP), 128>>>(x, W1, b1);
    ffn_kernel<false><<<dim3(D_OUT / 128, N_TOK / 128, N_EXP), 128>>>(x, W2, b2);
    combine_kernel<<<N_TOK, 128>>>(out);
}

// round 3
// speedup vs baseline: 1.5261x; 1.5261x over previous
#include <cuda_runtime.h>
#include <cuda_fp16.h>
#include <cstdint>

#define N_TOK 4096
#define D_IN  1024
#define D_HID 4096
#define D_OUT 1024
#define N_EXP 8

// ---------------- scratch (device globals; no runtime allocation) ----------------
__device__ __half g_Xh[(size_t)N_TOK * D_IN];            // x in fp16
__device__ __half g_W1h[(size_t)N_EXP * D_HID * D_IN];   // W1^T per expert: [e][N=4096][K=1024]
__device__ __half g_W2h[(size_t)N_EXP * D_OUT * D_HID];  // W2^T per expert: [e][N=1024][K=4096]
__device__ __half g_Hh[(size_t)N_TOK * 2 * D_HID];       // hidden acts fp16 per slot
__device__ float  g_Y[(size_t)N_TOK * 2 * D_OUT];        // expert outputs fp32 per slot
__device__ float  g_topk_w[N_TOK * 2];
__device__ int    g_count[N_EXP];
__device__ int    g_slots[N_EXP * N_TOK];                // slot = 2*token + k

// ---------------- helpers ----------------
__device__ __forceinline__ uint32_t sptr(const void* p) {
    return (uint32_t)__cvta_generic_to_shared(p);
}
__device__ __forceinline__ void cpa8(uint32_t s, const void* g) {
    asm volatile("cp.async.ca.shared.global [%0], [%1], 8;\n" :: "r"(s), "l"(g));
}
__device__ __forceinline__ void mma_f16(float* d, const uint32_t* a, const uint32_t* b) {
    asm volatile(
        "mma.sync.aligned.m16n8k16.row.col.f32.f16.f16.f32 "
        "{%0,%1,%2,%3}, {%4,%5,%6,%7}, {%8,%9}, {%0,%1,%2,%3};"
        : "+f"(d[0]), "+f"(d[1]), "+f"(d[2]), "+f"(d[3])
        : "r"(a[0]), "r"(a[1]), "r"(a[2]), "r"(a[3]),
          "r"(b[0]), "r"(b[1]));
}

// ---------------- init: zero expert counters ----------------
__global__ void init_kernel() {
    if (threadIdx.x < N_EXP) g_count[threadIdx.x] = 0;
}

// ---------------- x -> fp16 (dst referenced in DEVICE code only) ----------------
__global__ void convert_x_kernel(const float* __restrict__ x) {
    int i = blockIdx.x * blockDim.x + threadIdx.x;   // over float4s
    float4 v = ((const float4*)x)[i];
    ((half2*)g_Xh)[2 * i]     = __floats2half2_rn(v.x, v.y);
    ((half2*)g_Xh)[2 * i + 1] = __floats2half2_rn(v.z, v.w);
}

// ---------------- W [e][K][N] fp32 -> [e][N][K] fp16 (tiled transpose) ----------------
// NOTE: destination is selected INSIDE the kernel (device context). Passing a
// __device__ global as a host-side launch argument takes the host shadow
// symbol's address — on GB300 (ATS) that silently writes host memory. (R2 bug.)
template <int K, int N, bool FIRST>
__global__ void conv_transpose_kernel(const float* __restrict__ src) {
    __shared__ float t[32][33];
    const int e = blockIdx.z;
    const float* S = src + (size_t)e * K * N;
    __half* D = (FIRST ? g_W1h : g_W2h) + (size_t)e * (size_t)N * K;
    const int n0 = blockIdx.x * 32, k0 = blockIdx.y * 32;
    const int tx = threadIdx.x, ty = threadIdx.y;   // 32 x 8
#pragma unroll
    for (int j = 0; j < 32; j += 8)
        t[ty + j][tx] = S[(size_t)(k0 + ty + j) * N + n0 + tx];
    __syncthreads();
#pragma unroll
    for (int j = 0; j < 32; j += 8)
        D[(size_t)(n0 + ty + j) * K + k0 + tx] = __float2half_rn(t[tx][ty + j]);
}

// ---------------- gating: softmax -> top2 -> renorm softmax -> scatter ----------------
__global__ void gating_kernel(const float* __restrict__ x,
                              const float* __restrict__ Wg,
                              const float* __restrict__ bg) {
    const int t    = blockIdx.x * 8 + (threadIdx.x >> 5);
    const int lane = threadIdx.x & 31;

    float acc[8];
#pragma unroll
    for (int e = 0; e < 8; e++) acc[e] = 0.f;

    const float* xr = x + (size_t)t * D_IN;
    for (int d = lane; d < D_IN; d += 32) {
        float xv = xr[d];
        float4 w0 = *(const float4*)(Wg + d * 8);
        float4 w1 = *(const float4*)(Wg + d * 8 + 4);
        acc[0] += xv * w0.x; acc[1] += xv * w0.y;
        acc[2] += xv * w0.z; acc[3] += xv * w0.w;
        acc[4] += xv * w1.x; acc[5] += xv * w1.y;
        acc[6] += xv * w1.z; acc[7] += xv * w1.w;
    }
#pragma unroll
    for (int off = 16; off > 0; off >>= 1)
#pragma unroll
        for (int e = 0; e < 8; e++)
            acc[e] += __shfl_xor_sync(0xFFFFFFFFu, acc[e], off);

    if (lane == 0) {
        float l[8];
#pragma unroll
        for (int e = 0; e < 8; e++) l[e] = acc[e] + bg[e];
        float mx = l[0];
#pragma unroll
        for (int e = 1; e < 8; e++) mx = fmaxf(mx, l[e]);
        float p[8], s = 0.f;
#pragma unroll
        for (int e = 0; e < 8; e++) { p[e] = expf(l[e] - mx); s += p[e]; }
        float inv = 1.f / s;
#pragma unroll
        for (int e = 0; e < 8; e++) p[e] *= inv;

        int i0 = 0; float v0 = p[0];
#pragma unroll
        for (int e = 1; e < 8; e++) if (p[e] > v0) { v0 = p[e]; i0 = e; }
        int i1 = -1; float v1 = -1.f;
#pragma unroll
        for (int e = 0; e < 8; e++) if (e != i0 && p[e] > v1) { v1 = p[e]; i1 = e; }

        float e1 = expf(v1 - v0);
        float den = 1.f / (1.f + e1);
        float w0 = den;
        float w1 = e1 * den;

        int p0 = atomicAdd(&g_count[i0], 1);
        g_slots[i0 * N_TOK + p0] = 2 * t;
        int p1 = atomicAdd(&g_count[i1], 1);
        g_slots[i1 * N_TOK + p1] = 2 * t + 1;
        g_topk_w[2 * t]     = w0;
        g_topk_w[2 * t + 1] = w1;
    }
}

// ---------------- grouped GEMM (fp16 mma.sync m16n8k16), 128x128x32 tiles ----------------
// FIRST=true : A = gathered x rows (fp16) [cnt,1024],  B = W1^T[e] [4096,1024], relu(.+b1) -> g_Hh (fp16)
// FIRST=false: A = gathered g_Hh rows     [cnt,4096],  B = W2^T[e] [1024,4096], .+b2      -> g_Y  (fp32)
template <bool FIRST>
__global__ void __launch_bounds__(128, 2)
ffn_kernel(const float* __restrict__ Bias) {
    constexpr int K  = FIRST ? D_IN : D_HID;
    constexpr int N  = FIRST ? D_HID : D_OUT;
    constexpr int BM = 128, BN = 128, BK = 32;
    constexpr int STR = BK + 8;   // 40 halves
    constexpr int NS = K / BK;

    const int e   = blockIdx.z;
    const int cnt = g_count[e];
    const int m0  = blockIdx.y * BM;
    if (m0 >= cnt) return;
    const int rows = min(BM, cnt - m0);
    const int n0   = blockIdx.x * BN;

    const int tid  = threadIdx.x;
    const int lane = tid & 31;
    const int warp = tid >> 5;
    const int gid  = lane >> 2;   // 0..7
    const int itg  = lane & 3;    // 0..3
    const int wm = warp >> 1;     // 0..1 over M
    const int wn = warp & 1;      // 0..1 over N

    __shared__ __half sA[2][BM * STR];
    __shared__ __half sB[2][BN * STR];
    __shared__ int    sSlot[BM];

    sSlot[tid] = g_slots[e * N_TOK + m0 + ((tid < rows) ? tid : 0)];
    __syncthreads();

    const __half* Wb = (FIRST ? g_W1h : g_W2h) + (size_t)e * (size_t)N * K + (size_t)n0 * K;

    auto stage = [&](int s, int b) {
        const int k0 = s * BK;
#pragma unroll
        for (int i = 0; i < 8; i++) {           // A: 128 rows x 32 halves (8B chunks)
            int idx = i * 128 + tid;
            int row = idx >> 3;
            int c4  = (idx & 7) * 4;
            int slot = sSlot[row];
            const __half* g = FIRST
                ? (g_Xh + (size_t)(slot >> 1) * D_IN  + k0 + c4)
                : (g_Hh + (size_t)slot        * D_HID + k0 + c4);
            cpa8(sptr(&sA[b][row * STR + c4]), g);
        }
#pragma unroll
        for (int i = 0; i < 8; i++) {           // B: 128 n-rows x 32 k-halves
            int idx = i * 128 + tid;
            int row = idx >> 3;
            int c4  = (idx & 7) * 4;
            cpa8(sptr(&sB[b][row * STR + c4]), Wb + (size_t)row * K + k0 + c4);
        }
    };

    float acc[4][8][4];
#pragma unroll
    for (int a = 0; a < 4; a++)
#pragma unroll
        for (int b = 0; b < 8; b++)
#pragma unroll
            for (int c = 0; c < 4; c++) acc[a][b][c] = 0.f;

    stage(0, 0);
    asm volatile("cp.async.commit_group;\n");

    for (int s = 0; s < NS; ++s) {
        if (s + 1 < NS) {
            stage(s + 1, (s + 1) & 1);
            asm volatile("cp.async.commit_group;\n");
            asm volatile("cp.async.wait_group 1;\n");
        } else {
            asm volatile("cp.async.wait_group 0;\n");
        }
        __syncthreads();

        const __half* A = sA[s & 1];
        const __half* B = sB[s & 1];
#pragma unroll
        for (int ks = 0; ks < BK / 16; ++ks) {
            uint32_t af[4][4];
#pragma unroll
            for (int mf = 0; mf < 4; ++mf) {
                int r = wm * 64 + mf * 16 + gid;
                int c = ks * 16 + itg * 2;
                af[mf][0] = *(const uint32_t*)&A[r       * STR + c];
                af[mf][1] = *(const uint32_t*)&A[(r + 8) * STR + c];
                af[mf][2] = *(const uint32_t*)&A[r       * STR + c + 8];
                af[mf][3] = *(const uint32_t*)&A[(r + 8) * STR + c + 8];
            }
            uint32_t bf[8][2];
#pragma unroll
            for (int nf = 0; nf < 8; ++nf) {
                int n = wn * 64 + nf * 8 + gid;
                int c = ks * 16 + itg * 2;
                bf[nf][0] = *(const uint32_t*)&B[n * STR + c];
                bf[nf][1] = *(const uint32_t*)&B[n * STR + c + 8];
            }
#pragma unroll
            for (int mf = 0; mf < 4; ++mf)
#pragma unroll
                for (int nf = 0; nf < 8; ++nf)
                    mma_f16(acc[mf][nf], af[mf], bf[nf]);
        }
        __syncthreads();
    }

    // epilogue: bias (+relu for layer 1), scatter to slot rows
#pragma unroll
    for (int mf = 0; mf < 4; ++mf) {
        int rl = wm * 64 + mf * 16 + gid;
#pragma unroll
        for (int nf = 0; nf < 8; ++nf) {
            int n = n0 + wn * 64 + nf * 8 + 2 * itg;
            float2 bv = *(const float2*)(Bias + (size_t)e * N + n);
            float v00 = acc[mf][nf][0] + bv.x;
            float v01 = acc[mf][nf][1] + bv.y;
            float v10 = acc[mf][nf][2] + bv.x;
            float v11 = acc[mf][nf][3] + bv.y;
            if (FIRST) {
                v00 = fmaxf(v00, 0.f); v01 = fmaxf(v01, 0.f);
                v10 = fmaxf(v10, 0.f); v11 = fmaxf(v11, 0.f);
                if (rl < rows) {
                    int slot = sSlot[rl];
                    *(half2*)(g_Hh + (size_t)slot * D_HID + n) = __floats2half2_rn(v00, v01);
                }
                if (rl + 8 < rows) {
                    int slot = sSlot[rl + 8];
                    *(half2*)(g_Hh + (size_t)slot * D_HID + n) = __floats2half2_rn(v10, v11);
                }
            } else {
                if (rl < rows) {
                    int slot = sSlot[rl];
                    *(float2*)(g_Y + (size_t)slot * D_OUT + n) = make_float2(v00, v01);
                }
                if (rl + 8 < rows) {
                    int slot = sSlot[rl + 8];
                    *(float2*)(g_Y + (size_t)slot * D_OUT + n) = make_float2(v10, v11);
                }
            }
        }
    }
}

// ---------------- combine: out[t] = w0*Y[2t] + w1*Y[2t+1] ----------------
__global__ void combine_kernel(float* __restrict__ out) {
    const int t = blockIdx.x;
    const float w0 = g_topk_w[2 * t];
    const float w1 = g_topk_w[2 * t + 1];
    const float4* y0 = (const float4*)(g_Y + (size_t)(2 * t)     * D_OUT);
    const float4* y1 = (const float4*)(g_Y + (size_t)(2 * t + 1) * D_OUT);
    float4* o = (float4*)(out + (size_t)t * D_OUT);
    for (int i = threadIdx.x; i < D_OUT / 4; i += blockDim.x) {
        float4 a = y0[i], b = y1[i];
        float4 r;
        r.x = w0 * a.x + w1 * b.x;
        r.y = w0 * a.y + w1 * b.y;
        r.z = w0 * a.z + w1 * b.z;
        r.w = w0 * a.w + w1 * b.w;
        o[i] = r;
    }
}

// ---------------- launch ----------------
extern "C" void kernel_launch(void* const* d_in, const int* in_sizes, int n_in,
                              void* d_out, int out_size) {
    const float* x  = (const float*)d_in[0];
    const float* W1 = (const float*)d_in[1];
    const float* b1 = (const float*)d_in[2];
    const float* W2 = (const float*)d_in[3];
    const float* b2 = (const float*)d_in[4];
    const float* Wg = (const float*)d_in[5];
    const float* bg = (const float*)d_in[6];
    float* out = (float*)d_out;

    init_kernel<<<1, 32>>>();
    convert_x_kernel<<<(N_TOK * D_IN / 4) / 256, 256>>>(x);
    conv_transpose_kernel<D_IN,  D_HID, true ><<<dim3(D_HID / 32, D_IN  / 32, N_EXP), dim3(32, 8)>>>(W1);
    conv_transpose_kernel<D_HID, D_OUT, false><<<dim3(D_OUT / 32, D_HID / 32, N_EXP), dim3(32, 8)>>>(W2);
    gating_kernel<<<N_TOK / 8, 256>>>(x, Wg, bg);
    ffn_kernel<true ><<<dim3(D_HID / 128, N_TOK / 128, N_EXP), 128>>>(b1);
    ffn_kernel<false><<<dim3(D_OUT / 128, N_TOK / 128, N_EXP), 128>>>(b2);
    combine_kernel<<<N_TOK, 128>>>(out);
}

// round 5
// speedup vs baseline: 1.8173x; 1.1908x over previous
#include <cuda_runtime.h>
#include <cuda_fp16.h>
#include <cstdint>

#define N_TOK 4096
#define D_IN  1024
#define D_HID 4096
#define D_OUT 1024
#define N_EXP 8

// ---------------- scratch (device globals; no runtime allocation) ----------------
__device__ __half g_Xh[(size_t)N_TOK * D_IN];            // x in fp16
__device__ __half g_W1h[(size_t)N_EXP * D_HID * D_IN];   // W1^T per expert: [e][N=4096][K=1024]
__device__ __half g_W2h[(size_t)N_EXP * D_OUT * D_HID];  // W2^T per expert: [e][N=1024][K=4096]
__device__ __half g_Hh[(size_t)N_TOK * 2 * D_HID];       // hidden acts fp16 per slot
__device__ float  g_Y[(size_t)N_TOK * 2 * D_OUT];        // expert outputs fp32 per slot
__device__ float  g_topk_w[N_TOK * 2];
__device__ int    g_count[N_EXP];
__device__ int    g_slots[N_EXP * N_TOK];                // slot = 2*token + k

// ---------------- helpers ----------------
__device__ __forceinline__ uint32_t s2u(const void* p) {
    return (uint32_t)__cvta_generic_to_shared(p);
}
__device__ __forceinline__ void cpa16(uint32_t d, const void* g) {
    asm volatile("cp.async.cg.shared.global [%0], [%1], 16;\n" :: "r"(d), "l"(g));
}
#define LDSM_X4(r, a) \
    asm volatile("ldmatrix.sync.aligned.m8n8.x4.shared.b16 {%0,%1,%2,%3}, [%4];" \
        : "=r"((r)[0]), "=r"((r)[1]), "=r"((r)[2]), "=r"((r)[3]) : "r"(a))

__device__ __forceinline__ void mma_f16(float* d, const uint32_t* a, const uint32_t* b) {
    asm volatile(
        "mma.sync.aligned.m16n8k16.row.col.f32.f16.f16.f32 "
        "{%0,%1,%2,%3}, {%4,%5,%6,%7}, {%8,%9}, {%0,%1,%2,%3};"
        : "+f"(d[0]), "+f"(d[1]), "+f"(d[2]), "+f"(d[3])
        : "r"(a[0]), "r"(a[1]), "r"(a[2]), "r"(a[3]),
          "r"(b[0]), "r"(b[1]));
}

// ---------------- init: zero expert counters ----------------
__global__ void init_kernel() {
    if (threadIdx.x < N_EXP) g_count[threadIdx.x] = 0;
}

// ---------------- x -> fp16 ----------------
__global__ void convert_x_kernel(const float* __restrict__ x) {
    int i = blockIdx.x * blockDim.x + threadIdx.x;   // over float4s
    float4 v = ((const float4*)x)[i];
    ((half2*)g_Xh)[2 * i]     = __floats2half2_rn(v.x, v.y);
    ((half2*)g_Xh)[2 * i + 1] = __floats2half2_rn(v.z, v.w);
}

// ---------------- W [e][K][N] fp32 -> [e][N][K] fp16 (tiled transpose) ----------------
// Destination selected INSIDE the kernel (device context) — see R2 bug note.
template <int K, int N, bool FIRST>
__global__ void conv_transpose_kernel(const float* __restrict__ src) {
    __shared__ float t[32][33];
    const int e = blockIdx.z;
    const float* S = src + (size_t)e * K * N;
    __half* D = (FIRST ? g_W1h : g_W2h) + (size_t)e * (size_t)N * K;
    const int n0 = blockIdx.x * 32, k0 = blockIdx.y * 32;
    const int tx = threadIdx.x, ty = threadIdx.y;   // 32 x 8
#pragma unroll
    for (int j = 0; j < 32; j += 8)
        t[ty + j][tx] = S[(size_t)(k0 + ty + j) * N + n0 + tx];
    __syncthreads();
#pragma unroll
    for (int j = 0; j < 32; j += 8)
        D[(size_t)(n0 + ty + j) * K + k0 + tx] = __float2half_rn(t[tx][ty + j]);
}

// ---------------- gating: softmax -> top2 -> renorm softmax -> scatter ----------------
__global__ void gating_kernel(const float* __restrict__ x,
                              const float* __restrict__ Wg,
                              const float* __restrict__ bg) {
    const int t    = blockIdx.x * 8 + (threadIdx.x >> 5);
    const int lane = threadIdx.x & 31;

    float acc[8];
#pragma unroll
    for (int e = 0; e < 8; e++) acc[e] = 0.f;

    const float* xr = x + (size_t)t * D_IN;
    for (int d = lane; d < D_IN; d += 32) {
        float xv = xr[d];
        float4 w0 = *(const float4*)(Wg + d * 8);
        float4 w1 = *(const float4*)(Wg + d * 8 + 4);
        acc[0] += xv * w0.x; acc[1] += xv * w0.y;
        acc[2] += xv * w0.z; acc[3] += xv * w0.w;
        acc[4] += xv * w1.x; acc[5] += xv * w1.y;
        acc[6] += xv * w1.z; acc[7] += xv * w1.w;
    }
#pragma unroll
    for (int off = 16; off > 0; off >>= 1)
#pragma unroll
        for (int e = 0; e < 8; e++)
            acc[e] += __shfl_xor_sync(0xFFFFFFFFu, acc[e], off);

    if (lane == 0) {
        float l[8];
#pragma unroll
        for (int e = 0; e < 8; e++) l[e] = acc[e] + bg[e];
        float mx = l[0];
#pragma unroll
        for (int e = 1; e < 8; e++) mx = fmaxf(mx, l[e]);
        float p[8], s = 0.f;
#pragma unroll
        for (int e = 0; e < 8; e++) { p[e] = expf(l[e] - mx); s += p[e]; }
        float inv = 1.f / s;
#pragma unroll
        for (int e = 0; e < 8; e++) p[e] *= inv;

        int i0 = 0; float v0 = p[0];
#pragma unroll
        for (int e = 1; e < 8; e++) if (p[e] > v0) { v0 = p[e]; i0 = e; }
        int i1 = -1; float v1 = -1.f;
#pragma unroll
        for (int e = 0; e < 8; e++) if (e != i0 && p[e] > v1) { v1 = p[e]; i1 = e; }

        float e1 = expf(v1 - v0);
        float den = 1.f / (1.f + e1);
        float w0 = den;
        float w1 = e1 * den;

        int p0 = atomicAdd(&g_count[i0], 1);
        g_slots[i0 * N_TOK + p0] = 2 * t;
        int p1 = atomicAdd(&g_count[i1], 1);
        g_slots[i1 * N_TOK + p1] = 2 * t + 1;
        g_topk_w[2 * t]     = w0;
        g_topk_w[2 * t + 1] = w1;
    }
}

// ---------------- grouped GEMM (fp16 mma.sync + ldmatrix), 128x128x64 tiles ----------------
// FIRST=true : A = gathered x (fp16) [cnt,1024], B = W1^T[e] [4096,1024], relu(.+b1) -> g_Hh
// FIRST=false: A = gathered g_Hh     [cnt,4096], B = W2^T[e] [1024,4096], .+b2       -> g_Y
template <bool FIRST>
__global__ void __launch_bounds__(128, 2)
ffn_kernel(const float* __restrict__ Bias) {
    constexpr int K  = FIRST ? D_IN : D_HID;
    constexpr int N  = FIRST ? D_HID : D_OUT;
    constexpr int BM = 128, BK = 64;
    constexpr int STRB = (BK + 8) * 2;     // 144 bytes/row: conflict-free for ldmatrix + cp.async
    constexpr int NS = K / BK;
    constexpr int ASTG = BM * STRB;        // 18432 bytes per stage (A and B identical)

    constexpr int OFF_SLOT = 0;            // 128 ints
    constexpr int OFF_A    = 1024;         // 2 stages
    constexpr int OFF_B    = 1024 + 2 * ASTG;
    // total = 1024 + 4*18432 = 74752

    extern __shared__ __align__(128) char smem[];
    const uint32_t su = s2u(smem);

    const int e   = blockIdx.z;
    const int cnt = g_count[e];
    const int m0  = blockIdx.y * BM;
    if (m0 >= cnt) return;
    const int rows = min(BM, cnt - m0);
    const int n0   = blockIdx.x * 128;

    const int tid  = threadIdx.x;
    const int lane = tid & 31;
    const int warp = tid >> 5;
    const int gid  = lane >> 2;   // 0..7
    const int itg  = lane & 3;    // 0..3
    const int wm = warp >> 1;     // 0..1 over M (64 rows each)
    const int wn = warp & 1;      // 0..1 over N (64 cols each)

    int* sSlot = (int*)(smem + OFF_SLOT);
    sSlot[tid] = g_slots[e * N_TOK + m0 + ((tid < rows) ? tid : 0)];
    __syncthreads();

    const __half* Wb = (FIRST ? g_W1h : g_W2h)
                     + (size_t)e * (size_t)N * K + (size_t)n0 * K;

    auto stage = [&](int s) {
        const int k0 = s * BK;
        const uint32_t ab = su + OFF_A + (s & 1) * ASTG;
        const uint32_t bb = su + OFF_B + (s & 1) * ASTG;
#pragma unroll
        for (int it = 0; it < 8; it++) {        // A: 128 rows x 4 x 16B chunks... (8 iters x 128 thr)
            int idx = it * 128 + tid;
            int row = idx >> 3, c = idx & 7;    // c: 16B chunk within 128B row
            int slot = sSlot[row];
            const __half* g = FIRST
                ? g_Xh + (size_t)(slot >> 1) * D_IN  + k0 + c * 8
                : g_Hh + (size_t)slot        * D_HID + k0 + c * 8;
            cpa16(ab + row * STRB + c * 16, g);
        }
#pragma unroll
        for (int it = 0; it < 8; it++) {        // B: 128 n-rows x 64 k-halves
            int idx = it * 128 + tid;
            int row = idx >> 3, c = idx & 7;
            cpa16(bb + row * STRB + c * 16, Wb + (size_t)row * K + k0 + c * 8);
        }
        asm volatile("cp.async.commit_group;\n");
    };

    float acc[4][8][4];
#pragma unroll
    for (int a = 0; a < 4; a++)
#pragma unroll
        for (int b = 0; b < 8; b++)
#pragma unroll
            for (int c = 0; c < 4; c++) acc[a][b][c] = 0.f;

    // lane-fixed parts of ldmatrix addresses
    const uint32_t aLane = (uint32_t)((wm * 64 + (lane & 15)) * STRB + (lane >> 4) * 16);
    const uint32_t bLane = (uint32_t)((wn * 64 + (lane & 7) + ((lane & 16) ? 8 : 0)) * STRB
                                      + ((lane & 8) ? 16 : 0));

    stage(0);
    for (int s = 0; s < NS; ++s) {
        if (s + 1 < NS) {
            stage(s + 1);
            asm volatile("cp.async.wait_group 1;\n");
        } else {
            asm volatile("cp.async.wait_group 0;\n");
        }
        __syncthreads();

        const uint32_t aS = su + OFF_A + (s & 1) * ASTG + aLane;
        const uint32_t bS = su + OFF_B + (s & 1) * ASTG + bLane;
#pragma unroll
        for (int ks = 0; ks < BK / 16; ++ks) {   // 4 k16-steps
            uint32_t af[4][4];
#pragma unroll
            for (int mf = 0; mf < 4; ++mf)
                LDSM_X4(af[mf], aS + ks * 32 + mf * 16 * STRB);
            uint32_t bf[4][4];
#pragma unroll
            for (int p = 0; p < 4; ++p)
                LDSM_X4(bf[p], bS + ks * 32 + p * 16 * STRB);
#pragma unroll
            for (int mf = 0; mf < 4; ++mf)
#pragma unroll
                for (int p = 0; p < 4; ++p) {
                    mma_f16(acc[mf][2 * p],     af[mf], &bf[p][0]);
                    mma_f16(acc[mf][2 * p + 1], af[mf], &bf[p][2]);
                }
        }
        __syncthreads();
    }

    // epilogue: bias (+relu for layer 1), scatter to slot rows
#pragma unroll
    for (int mf = 0; mf < 4; ++mf) {
        int rl = wm * 64 + mf * 16 + gid;
#pragma unroll
        for (int nf = 0; nf < 8; ++nf) {
            int n = n0 + wn * 64 + nf * 8 + 2 * itg;
            float2 bv = *(const float2*)(Bias + (size_t)e * N + n);
            float v00 = acc[mf][nf][0] + bv.x;
            float v01 = acc[mf][nf][1] + bv.y;
            float v10 = acc[mf][nf][2] + bv.x;
            float v11 = acc[mf][nf][3] + bv.y;
            if (FIRST) {
                v00 = fmaxf(v00, 0.f); v01 = fmaxf(v01, 0.f);
                v10 = fmaxf(v10, 0.f); v11 = fmaxf(v11, 0.f);
                if (rl < rows) {
                    int slot = sSlot[rl];
                    *(half2*)(g_Hh + (size_t)slot * D_HID + n) = __floats2half2_rn(v00, v01);
                }
                if (rl + 8 < rows) {
                    int slot = sSlot[rl + 8];
                    *(half2*)(g_Hh + (size_t)slot * D_HID + n) = __floats2half2_rn(v10, v11);
                }
            } else {
                if (rl < rows) {
                    int slot = sSlot[rl];
                    *(float2*)(g_Y + (size_t)slot * D_OUT + n) = make_float2(v00, v01);
                }
                if (rl + 8 < rows) {
                    int slot = sSlot[rl + 8];
                    *(float2*)(g_Y + (size_t)slot * D_OUT + n) = make_float2(v10, v11);
                }
            }
        }
    }
}

// ---------------- combine: out[t] = w0*Y[2t] + w1*Y[2t+1] ----------------
__global__ void combine_kernel(float* __restrict__ out) {
    const int t = blockIdx.x;
    const float w0 = g_topk_w[2 * t];
    const float w1 = g_topk_w[2 * t + 1];
    const float4* y0 = (const float4*)(g_Y + (size_t)(2 * t)     * D_OUT);
    const float4* y1 = (const float4*)(g_Y + (size_t)(2 * t + 1) * D_OUT);
    float4* o = (float4*)(out + (size_t)t * D_OUT);
    for (int i = threadIdx.x; i < D_OUT / 4; i += blockDim.x) {
        float4 a = y0[i], b = y1[i];
        float4 r;
        r.x = w0 * a.x + w1 * b.x;
        r.y = w0 * a.y + w1 * b.y;
        r.z = w0 * a.z + w1 * b.z;
        r.w = w0 * a.w + w1 * b.w;
        o[i] = r;
    }
}

// ---------------- launch ----------------
extern "C" void kernel_launch(void* const* d_in, const int* in_sizes, int n_in,
                              void* d_out, int out_size) {
    const float* x  = (const float*)d_in[0];
    const float* W1 = (const float*)d_in[1];
    const float* b1 = (const float*)d_in[2];
    const float* W2 = (const float*)d_in[3];
    const float* b2 = (const float*)d_in[4];
    const float* Wg = (const float*)d_in[5];
    const float* bg = (const float*)d_in[6];
    float* out = (float*)d_out;

    constexpr int SMEM_FFN = 1024 + 4 * 128 * 144;   // 74752
    cudaFuncSetAttribute(ffn_kernel<true>,
                         cudaFuncAttributeMaxDynamicSharedMemorySize, SMEM_FFN);
    cudaFuncSetAttribute(ffn_kernel<false>,
                         cudaFuncAttributeMaxDynamicSharedMemorySize, SMEM_FFN);

    init_kernel<<<1, 32>>>();
    convert_x_kernel<<<(N_TOK * D_IN / 4) / 256, 256>>>(x);
    conv_transpose_kernel<D_IN,  D_HID, true ><<<dim3(D_HID / 32, D_IN  / 32, N_EXP), dim3(32, 8)>>>(W1);
    conv_transpose_kernel<D_HID, D_OUT, false><<<dim3(D_OUT / 32, D_HID / 32, N_EXP), dim3(32, 8)>>>(W2);
    gating_kernel<<<N_TOK / 8, 256>>>(x, Wg, bg);
    ffn_kernel<true ><<<dim3(D_HID / 128, N_TOK / 128, N_EXP), 128, SMEM_FFN>>>(b1);
    ffn_kernel<false><<<dim3(D_OUT / 128, N_TOK / 128, N_EXP), 128, SMEM_FFN>>>(b2);
    combine_kernel<<<N_TOK, 128>>>(out);
}

// round 6
// speedup vs baseline: 1.8513x; 1.0187x over previous
#include <cuda_runtime.h>
#include <cuda_fp16.h>
#include <cstdint>

#define N_TOK 4096
#define D_IN  1024
#define D_HID 4096
#define D_OUT 1024
#define N_EXP 8

// ---------------- scratch (device globals; no runtime allocation) ----------------
__device__ __half g_Xh[(size_t)N_TOK * D_IN];            // x in fp16
__device__ __half g_W1h[(size_t)N_EXP * D_HID * D_IN];   // W1^T per expert: [e][N=4096][K=1024]
__device__ __half g_W2h[(size_t)N_EXP * D_OUT * D_HID];  // W2^T per expert: [e][N=1024][K=4096]
__device__ __half g_Hh[(size_t)N_TOK * 2 * D_HID];       // hidden acts fp16 per slot
__device__ float  g_Y[(size_t)N_TOK * 2 * D_OUT];        // expert outputs fp32 per slot
__device__ float  g_topk_w[N_TOK * 2];
__device__ int    g_count[N_EXP];
__device__ int    g_slots[N_EXP * N_TOK];                // slot = 2*token + k

// ---------------- helpers ----------------
__device__ __forceinline__ uint32_t s2u(const void* p) {
    return (uint32_t)__cvta_generic_to_shared(p);
}
__device__ __forceinline__ void cpa16(uint32_t d, const void* g) {
    asm volatile("cp.async.cg.shared.global [%0], [%1], 16;\n" :: "r"(d), "l"(g));
}
// NON-volatile LDSM: "memory" clobber keeps it ordered vs barriers/smem writes,
// but ptxas is free to interleave it with (pure-register) HMMAs.
#define LDSM_X4(r, a) \
    asm("ldmatrix.sync.aligned.m8n8.x4.shared.b16 {%0,%1,%2,%3}, [%4];" \
        : "=r"((r)[0]), "=r"((r)[1]), "=r"((r)[2]), "=r"((r)[3]) : "r"(a) : "memory")

// NON-volatile MMA: pure register op, fully schedulable.
__device__ __forceinline__ void mma_f16(float* d, const uint32_t* a, const uint32_t* b) {
    asm("mma.sync.aligned.m16n8k16.row.col.f32.f16.f16.f32 "
        "{%0,%1,%2,%3}, {%4,%5,%6,%7}, {%8,%9}, {%0,%1,%2,%3};"
        : "+f"(d[0]), "+f"(d[1]), "+f"(d[2]), "+f"(d[3])
        : "r"(a[0]), "r"(a[1]), "r"(a[2]), "r"(a[3]),
          "r"(b[0]), "r"(b[1]));
}

// ---------------- init: zero expert counters ----------------
__global__ void init_kernel() {
    if (threadIdx.x < N_EXP) g_count[threadIdx.x] = 0;
}

// ---------------- x -> fp16 ----------------
__global__ void convert_x_kernel(const float* __restrict__ x) {
    int i = blockIdx.x * blockDim.x + threadIdx.x;   // over float4s
    float4 v = ((const float4*)x)[i];
    ((half2*)g_Xh)[2 * i]     = __floats2half2_rn(v.x, v.y);
    ((half2*)g_Xh)[2 * i + 1] = __floats2half2_rn(v.z, v.w);
}

// ---------------- W [e][K][N] fp32 -> [e][N][K] fp16, 64x64 tiles, 128B writes ----------------
// Destination selected INSIDE the kernel (device context) — see R2 bug note.
template <int K, int N, bool FIRST>
__global__ void conv_transpose_kernel(const float* __restrict__ src) {
    __shared__ float t[64][65];
    const int e = blockIdx.z;
    const float* S = src + (size_t)e * K * N;
    __half* D = (FIRST ? g_W1h : g_W2h) + (size_t)e * (size_t)N * K;
    const int n0 = blockIdx.x * 64, k0 = blockIdx.y * 64;
    const int tx = threadIdx.x, ty = threadIdx.y;   // 32 x 8

#pragma unroll
    for (int j = 0; j < 64; j += 8) {
        t[ty + j][tx]      = S[(size_t)(k0 + ty + j) * N + n0 + tx];
        t[ty + j][tx + 32] = S[(size_t)(k0 + ty + j) * N + n0 + tx + 32];
    }
    __syncthreads();
    // write D rows: 64 contiguous halves = 128B per warp-row (full-sector stores)
#pragma unroll
    for (int j = 0; j < 64; j += 8) {
        int nr = ty + j;
        half2 v = __floats2half2_rn(t[2 * tx][nr], t[2 * tx + 1][nr]);
        *(half2*)(D + (size_t)(n0 + nr) * K + k0 + 2 * tx) = v;
    }
}

// ---------------- gating: softmax -> top2 -> renorm softmax -> scatter ----------------
__global__ void gating_kernel(const float* __restrict__ x,
                              const float* __restrict__ Wg,
                              const float* __restrict__ bg) {
    const int t    = blockIdx.x * 8 + (threadIdx.x >> 5);
    const int lane = threadIdx.x & 31;

    float acc[8];
#pragma unroll
    for (int e = 0; e < 8; e++) acc[e] = 0.f;

    const float* xr = x + (size_t)t * D_IN;
    for (int d = lane; d < D_IN; d += 32) {
        float xv = xr[d];
        float4 w0 = *(const float4*)(Wg + d * 8);
        float4 w1 = *(const float4*)(Wg + d * 8 + 4);
        acc[0] += xv * w0.x; acc[1] += xv * w0.y;
        acc[2] += xv * w0.z; acc[3] += xv * w0.w;
        acc[4] += xv * w1.x; acc[5] += xv * w1.y;
        acc[6] += xv * w1.z; acc[7] += xv * w1.w;
    }
#pragma unroll
    for (int off = 16; off > 0; off >>= 1)
#pragma unroll
        for (int e = 0; e < 8; e++)
            acc[e] += __shfl_xor_sync(0xFFFFFFFFu, acc[e], off);

    if (lane == 0) {
        float l[8];
#pragma unroll
        for (int e = 0; e < 8; e++) l[e] = acc[e] + bg[e];
        float mx = l[0];
#pragma unroll
        for (int e = 1; e < 8; e++) mx = fmaxf(mx, l[e]);
        float p[8], s = 0.f;
#pragma unroll
        for (int e = 0; e < 8; e++) { p[e] = expf(l[e] - mx); s += p[e]; }
        float inv = 1.f / s;
#pragma unroll
        for (int e = 0; e < 8; e++) p[e] *= inv;

        int i0 = 0; float v0 = p[0];
#pragma unroll
        for (int e = 1; e < 8; e++) if (p[e] > v0) { v0 = p[e]; i0 = e; }
        int i1 = -1; float v1 = -1.f;
#pragma unroll
        for (int e = 0; e < 8; e++) if (e != i0 && p[e] > v1) { v1 = p[e]; i1 = e; }

        float e1 = expf(v1 - v0);
        float den = 1.f / (1.f + e1);
        float w0 = den;
        float w1 = e1 * den;

        int p0 = atomicAdd(&g_count[i0], 1);
        g_slots[i0 * N_TOK + p0] = 2 * t;
        int p1 = atomicAdd(&g_count[i1], 1);
        g_slots[i1 * N_TOK + p1] = 2 * t + 1;
        g_topk_w[2 * t]     = w0;
        g_topk_w[2 * t + 1] = w1;
    }
}

// ---------------- grouped GEMM (fp16 mma.sync + ldmatrix), 128x128x64 tiles ----------------
// FIRST=true : A = gathered x (fp16) [cnt,1024], B = W1^T[e] [4096,1024], relu(.+b1) -> g_Hh
// FIRST=false: A = gathered g_Hh     [cnt,4096], B = W2^T[e] [1024,4096], .+b2       -> g_Y
template <bool FIRST>
__global__ void __launch_bounds__(128, 2)
ffn_kernel(const float* __restrict__ Bias) {
    constexpr int K  = FIRST ? D_IN : D_HID;
    constexpr int N  = FIRST ? D_HID : D_OUT;
    constexpr int BM = 128, BK = 64;
    constexpr int STRB = (BK + 8) * 2;     // 144 bytes/row: conflict-free for ldmatrix + cp.async
    constexpr int NS = K / BK;
    constexpr int ASTG = BM * STRB;        // 18432 bytes per stage (A and B identical)

    constexpr int OFF_SLOT = 0;            // 128 ints
    constexpr int OFF_A    = 1024;         // 2 stages
    constexpr int OFF_B    = 1024 + 2 * ASTG;

    extern __shared__ __align__(128) char smem[];
    const uint32_t su = s2u(smem);

    const int e   = blockIdx.z;
    const int cnt = g_count[e];
    const int m0  = blockIdx.y * BM;
    if (m0 >= cnt) return;
    const int rows = min(BM, cnt - m0);
    const int n0   = blockIdx.x * 128;

    const int tid  = threadIdx.x;
    const int lane = tid & 31;
    const int warp = tid >> 5;
    const int gid  = lane >> 2;   // 0..7
    const int itg  = lane & 3;    // 0..3
    const int wm = warp >> 1;     // 0..1 over M (64 rows each)
    const int wn = warp & 1;      // 0..1 over N (64 cols each)

    int* sSlot = (int*)(smem + OFF_SLOT);
    sSlot[tid] = g_slots[e * N_TOK + m0 + ((tid < rows) ? tid : 0)];
    __syncthreads();

    const __half* Wb = (FIRST ? g_W1h : g_W2h)
                     + (size_t)e * (size_t)N * K + (size_t)n0 * K;

    auto stage = [&](int s) {
        const int k0 = s * BK;
        const uint32_t ab = su + OFF_A + (s & 1) * ASTG;
        const uint32_t bb = su + OFF_B + (s & 1) * ASTG;
#pragma unroll
        for (int it = 0; it < 8; it++) {        // A: 128 rows x 64 halves
            int idx = it * 128 + tid;
            int row = idx >> 3, c = idx & 7;
            int slot = sSlot[row];
            const __half* g = FIRST
                ? g_Xh + (size_t)(slot >> 1) * D_IN  + k0 + c * 8
                : g_Hh + (size_t)slot        * D_HID + k0 + c * 8;
            cpa16(ab + row * STRB + c * 16, g);
        }
#pragma unroll
        for (int it = 0; it < 8; it++) {        // B: 128 n-rows x 64 k-halves
            int idx = it * 128 + tid;
            int row = idx >> 3, c = idx & 7;
            cpa16(bb + row * STRB + c * 16, Wb + (size_t)row * K + k0 + c * 8);
        }
        asm volatile("cp.async.commit_group;\n");
    };

    float acc[4][8][4];
#pragma unroll
    for (int a = 0; a < 4; a++)
#pragma unroll
        for (int b = 0; b < 8; b++)
#pragma unroll
            for (int c = 0; c < 4; c++) acc[a][b][c] = 0.f;

    // lane-fixed parts of ldmatrix addresses
    const uint32_t aLane = (uint32_t)((wm * 64 + (lane & 15)) * STRB + (lane >> 4) * 16);
    const uint32_t bLane = (uint32_t)((wn * 64 + (lane & 7) + ((lane & 16) ? 8 : 0)) * STRB
                                      + ((lane & 8) ? 16 : 0));

    stage(0);
    for (int s = 0; s < NS; ++s) {
        if (s + 1 < NS) {
            stage(s + 1);
            asm volatile("cp.async.wait_group 1;\n");
        } else {
            asm volatile("cp.async.wait_group 0;\n");
        }
        __syncthreads();

        const uint32_t aS = su + OFF_A + (s & 1) * ASTG + aLane;
        const uint32_t bS = su + OFF_B + (s & 1) * ASTG + bLane;

        // software-pipelined fragments: LDSM for ks+1 issued before HMMAs of ks
        uint32_t af[2][4][4], bf[2][4][4];
#pragma unroll
        for (int mf = 0; mf < 4; ++mf) LDSM_X4(af[0][mf], aS + mf * 16 * STRB);
#pragma unroll
        for (int p = 0; p < 4; ++p)    LDSM_X4(bf[0][p],  bS + p * 16 * STRB);

#pragma unroll
        for (int ks = 0; ks < BK / 16; ++ks) {
            const int cur = ks & 1, nxt = cur ^ 1;
            if (ks + 1 < BK / 16) {
#pragma unroll
                for (int mf = 0; mf < 4; ++mf)
                    LDSM_X4(af[nxt][mf], aS + (ks + 1) * 32 + mf * 16 * STRB);
#pragma unroll
                for (int p = 0; p < 4; ++p)
                    LDSM_X4(bf[nxt][p],  bS + (ks + 1) * 32 + p * 16 * STRB);
            }
#pragma unroll
            for (int mf = 0; mf < 4; ++mf)
#pragma unroll
                for (int p = 0; p < 4; ++p) {
                    mma_f16(acc[mf][2 * p],     af[cur][mf], &bf[cur][p][0]);
                    mma_f16(acc[mf][2 * p + 1], af[cur][mf], &bf[cur][p][2]);
                }
        }
        __syncthreads();
    }

    // epilogue: bias (+relu for layer 1), scatter to slot rows
#pragma unroll
    for (int mf = 0; mf < 4; ++mf) {
        int rl = wm * 64 + mf * 16 + gid;
#pragma unroll
        for (int nf = 0; nf < 8; ++nf) {
            int n = n0 + wn * 64 + nf * 8 + 2 * itg;
            float2 bv = *(const float2*)(Bias + (size_t)e * N + n);
            float v00 = acc[mf][nf][0] + bv.x;
            float v01 = acc[mf][nf][1] + bv.y;
            float v10 = acc[mf][nf][2] + bv.x;
            float v11 = acc[mf][nf][3] + bv.y;
            if (FIRST) {
                v00 = fmaxf(v00, 0.f); v01 = fmaxf(v01, 0.f);
                v10 = fmaxf(v10, 0.f); v11 = fmaxf(v11, 0.f);
                if (rl < rows) {
                    int slot = sSlot[rl];
                    *(half2*)(g_Hh + (size_t)slot * D_HID + n) = __floats2half2_rn(v00, v01);
                }
                if (rl + 8 < rows) {
                    int slot = sSlot[rl + 8];
                    *(half2*)(g_Hh + (size_t)slot * D_HID + n) = __floats2half2_rn(v10, v11);
                }
            } else {
                if (rl < rows) {
                    int slot = sSlot[rl];
                    *(float2*)(g_Y + (size_t)slot * D_OUT + n) = make_float2(v00, v01);
                }
                if (rl + 8 < rows) {
                    int slot = sSlot[rl + 8];
                    *(float2*)(g_Y + (size_t)slot * D_OUT + n) = make_float2(v10, v11);
                }
            }
        }
    }
}

// ---------------- combine: out[t] = w0*Y[2t] + w1*Y[2t+1] ----------------
__global__ void combine_kernel(float* __restrict__ out) {
    const int t = blockIdx.x;
    const float w0 = g_topk_w[2 * t];
    const float w1 = g_topk_w[2 * t + 1];
    const float4* y0 = (const float4*)(g_Y + (size_t)(2 * t)     * D_OUT);
    const float4* y1 = (const float4*)(g_Y + (size_t)(2 * t + 1) * D_OUT);
    float4* o = (float4*)(out + (size_t)t * D_OUT);
    for (int i = threadIdx.x; i < D_OUT / 4; i += blockDim.x) {
        float4 a = y0[i], b = y1[i];
        float4 r;
        r.x = w0 * a.x + w1 * b.x;
        r.y = w0 * a.y + w1 * b.y;
        r.z = w0 * a.z + w1 * b.z;
        r.w = w0 * a.w + w1 * b.w;
        o[i] = r;
    }
}

// ---------------- launch ----------------
extern "C" void kernel_launch(void* const* d_in, const int* in_sizes, int n_in,
                              void* d_out, int out_size) {
    const float* x  = (const float*)d_in[0];
    const float* W1 = (const float*)d_in[1];
    const float* b1 = (const float*)d_in[2];
    const float* W2 = (const float*)d_in[3];
    const float* b2 = (const float*)d_in[4];
    const float* Wg = (const float*)d_in[5];
    const float* bg = (const float*)d_in[6];
    float* out = (float*)d_out;

    constexpr int SMEM_FFN = 1024 + 4 * 128 * 144;   // 74752
    cudaFuncSetAttribute(ffn_kernel<true>,
                         cudaFuncAttributeMaxDynamicSharedMemorySize, SMEM_FFN);
    cudaFuncSetAttribute(ffn_kernel<false>,
                         cudaFuncAttributeMaxDynamicSharedMemorySize, SMEM_FFN);

    init_kernel<<<1, 32>>>();
    convert_x_kernel<<<(N_TOK * D_IN / 4) / 256, 256>>>(x);
    conv_transpose_kernel<D_IN,  D_HID, true ><<<dim3(D_HID / 64, D_IN  / 64, N_EXP), dim3(32, 8)>>>(W1);
    conv_transpose_kernel<D_HID, D_OUT, false><<<dim3(D_OUT / 64, D_HID / 64, N_EXP), dim3(32, 8)>>>(W2);
    gating_kernel<<<N_TOK / 8, 256>>>(x, Wg, bg);
    ffn_kernel<true ><<<dim3(D_HID / 128, N_TOK / 128, N_EXP), 128, SMEM_FFN>>>(b1);
    ffn_kernel<false><<<dim3(D_OUT / 128, N_TOK / 128, N_EXP), 128, SMEM_FFN>>>(b2);
    combine_kernel<<<N_TOK, 128>>>(out);
}